// round 3
// baseline (speedup 1.0000x reference)
#include <cuda_runtime.h>

// GRU persistent kernel: 512 dependent steps in ONE kernel, grid-wide
// sense-reversal barriers, weights SMEM-resident per hidden-slice CTA.
//
// Grid: 128 CTAs = 8 batch-tiles (32 rows) x 16 hidden-slices (16 cols).
// Block: 256 threads. Each thread owns (2 batch rows x 1 hidden col).
// Inner products use sm_103a packed fma.rn.f32x2 (2x FFMA-3reg rate).

#define SEQLEN  512
#define BATCHN  256
#define INPUTN  128
#define HID     256
#define NBLK    128
#define NBT     8      // batch tiles
#define BT      32     // rows per batch tile
#define HS      16     // hidden cols per slice
#define WPAD    388    // padded weight row (floats): 388%32=4 -> <=2-way LDS conflicts
#define WP16    (WPAD/4)        // 97 16B-chunks per row
#define GSTRIDE (HS*WPAD/4)     // 1552 16B-chunks per gate block

__device__ float    g_h [BATCHN * HID];
__device__ float    g_rh[BATCHN * HID];
__device__ unsigned g_count = 0;
__device__ unsigned g_sense = 0;

__device__ __forceinline__ void ffma2(unsigned long long &acc,
                                      unsigned long long a,
                                      unsigned long long b) {
    asm("fma.rn.f32x2 %0, %1, %2, %0;" : "+l"(acc) : "l"(a), "l"(b));
}

__device__ __forceinline__ float f2sum(unsigned long long v) {
    return __uint_as_float((unsigned)v) + __uint_as_float((unsigned)(v >> 32));
}

__device__ __forceinline__ float sigmoidf_(float a) {
    return 1.0f / (1.0f + __expf(-a));
}
// tanh(a) = 2*sigmoid(2a)-1 ; safe at both infinities (no NaN path)
__device__ __forceinline__ float tanhf_(float a) {
    return 2.0f / (1.0f + __expf(-2.0f * a)) - 1.0f;
}

// Split grid barrier: arrive (non-blocking) ... independent work ... wait.
// Sense is thread-0-local; initial value read from g_sense at kernel start,
// so state is consistent across graph replays (count always drains to 0).
__device__ __forceinline__ void grid_arrive(unsigned &sense) {
    __syncthreads();
    if (threadIdx.x == 0) {
        sense ^= 1u;
        __threadfence();                       // cumulative: orders CTA's writes
        unsigned prev = atomicAdd(&g_count, 1u);
        if (prev == NBLK - 1u) {
            atomicExch(&g_count, 0u);
            __threadfence();
            atomicExch(&g_sense, sense);       // release
        }
    }
}
__device__ __forceinline__ void grid_wait(unsigned sense) {
    if (threadIdx.x == 0) {
        while (*((volatile unsigned *)&g_sense) != sense) { }
        __threadfence();                       // acquire
    }
    __syncthreads();
}

__global__ void __launch_bounds__(256, 1)
gru_persistent(const float* __restrict__ X,
               const float* __restrict__ Wz, const float* __restrict__ bz,
               const float* __restrict__ Wr, const float* __restrict__ br,
               const float* __restrict__ Wc, const float* __restrict__ bc,
               float* __restrict__ out)
{
    extern __shared__ float sm[];
    float* sW   = sm;                         // 3 * 16 * 388 = 18624 floats
    float* sB   = sm + 3 * HS * WPAD;         // 48 floats (bz|br|bc)
    float* h_s  = sB + 48;                    // 32 x 256
    float* rh_s = h_s + BT * HID;             // 32 x 256
    float* x_s  = rh_s + BT * HID;            // 32 x 128

    const int tid   = threadIdx.x;
    const int bt    = blockIdx.x & (NBT - 1);
    const int hsb   = blockIdx.x >> 3;
    const int bbase = bt * BT;
    const int jbase = hsb * HS;

    unsigned sense = 0;
    if (tid == 0) sense = *((volatile unsigned *)&g_sense);

    // ---- load this CTA's weight slice into padded SMEM (once) ----
    {
        float4* sW4 = (float4*)sW;
        const float* Wsrc0 = Wz; const float* Wsrc1 = Wr; const float* Wsrc2 = Wc;
        #pragma unroll
        for (int g = 0; g < 3; g++) {
            const float* W = (g == 0) ? Wsrc0 : (g == 1) ? Wsrc1 : Wsrc2;
            const float4* W4 = (const float4*)W;
            for (int idx = tid; idx < HS * 96; idx += 256) {
                int j = idx / 96, k4 = idx % 96;
                sW4[g * GSTRIDE + j * WP16 + k4] = W4[(jbase + j) * 96 + k4];
            }
        }
        if (tid < HS) {
            sB[tid]          = bz[jbase + tid];
            sB[HS + tid]     = br[jbase + tid];
            sB[2 * HS + tid] = bc[jbase + tid];
        }
        for (int i = tid; i < BT * HID; i += 256) h_s[i] = 0.0f;  // h0 = 0
    }
    // x tile for t=0
    for (int idx = tid; idx < BT * (INPUTN / 4); idx += 256) {
        int row = idx >> 5, c4 = idx & 31;
        ((float4*)x_s)[row * 32 + c4] =
            ((const float4*)X)[(size_t)(bbase + row) * (SEQLEN * INPUTN / 4) + c4];
    }
    __syncthreads();

    const int ty = tid >> 4;
    const int tx = tid & 15;
    const int b0 = 2 * ty, b1 = 2 * ty + 1;
    const int jg = jbase + tx;

    const ulonglong2* h2  = (const ulonglong2*)h_s;
    const ulonglong2* rh2 = (const ulonglong2*)rh_s;
    const ulonglong2* x2  = (const ulonglong2*)x_s;
    const ulonglong2* wz2 = (const ulonglong2*)sW + tx * WP16;
    const ulonglong2* wr2 = wz2 + GSTRIDE;
    const ulonglong2* wc2 = wz2 + 2 * GSTRIDE;

    for (int t = 0; t < SEQLEN; t++) {
        // ================= phase 1: z, r =================
        unsigned long long az0 = 0, az1 = 0, ar0 = 0, ar1 = 0;
        #pragma unroll 8
        for (int k = 0; k < HID / 4; k++) {
            ulonglong2 hv0 = h2[b0 * (HID / 4) + k];
            ulonglong2 hv1 = h2[b1 * (HID / 4) + k];
            ulonglong2 wzv = wz2[k];
            ulonglong2 wrv = wr2[k];
            ffma2(az0, wzv.x, hv0.x); ffma2(az0, wzv.y, hv0.y);
            ffma2(ar0, wrv.x, hv0.x); ffma2(ar0, wrv.y, hv0.y);
            ffma2(az1, wzv.x, hv1.x); ffma2(az1, wzv.y, hv1.y);
            ffma2(ar1, wrv.x, hv1.x); ffma2(ar1, wrv.y, hv1.y);
        }
        #pragma unroll 8
        for (int k = 0; k < INPUTN / 4; k++) {
            ulonglong2 xv0 = x2[b0 * (INPUTN / 4) + k];
            ulonglong2 xv1 = x2[b1 * (INPUTN / 4) + k];
            ulonglong2 wzv = wz2[HID / 4 + k];
            ulonglong2 wrv = wr2[HID / 4 + k];
            ffma2(az0, wzv.x, xv0.x); ffma2(az0, wzv.y, xv0.y);
            ffma2(ar0, wrv.x, xv0.x); ffma2(ar0, wrv.y, xv0.y);
            ffma2(az1, wzv.x, xv1.x); ffma2(az1, wzv.y, xv1.y);
            ffma2(ar1, wrv.x, xv1.x); ffma2(ar1, wrv.y, xv1.y);
        }
        float z0 = sigmoidf_(f2sum(az0) + sB[tx]);
        float z1 = sigmoidf_(f2sum(az1) + sB[tx]);
        float r0 = sigmoidf_(f2sum(ar0) + sB[HS + tx]);
        float r1 = sigmoidf_(f2sum(ar1) + sB[HS + tx]);
        float h0old = h_s[b0 * HID + jg];
        float h1old = h_s[b1 * HID + jg];
        g_rh[(bbase + b0) * HID + jg] = r0 * h0old;
        g_rh[(bbase + b1) * HID + jg] = r1 * h1old;

        grid_arrive(sense);                      // barrier A (arrive)

        // overlap barrier A latency: candidate x-part (independent of rh)
        unsigned long long ac0 = 0, ac1 = 0;
        #pragma unroll 8
        for (int k = 0; k < INPUTN / 4; k++) {
            ulonglong2 xv0 = x2[b0 * (INPUTN / 4) + k];
            ulonglong2 xv1 = x2[b1 * (INPUTN / 4) + k];
            ulonglong2 wcv = wc2[HID / 4 + k];
            ffma2(ac0, wcv.x, xv0.x); ffma2(ac0, wcv.y, xv0.y);
            ffma2(ac1, wcv.x, xv1.x); ffma2(ac1, wcv.y, xv1.y);
        }

        grid_wait(sense);                        // barrier A (wait)

        // pull full r*h rows for our batch tile (written by all 16 slices)
        for (int idx = tid; idx < BT * (HID / 4); idx += 256)
            ((float4*)rh_s)[idx] = ((const float4*)g_rh)[bbase * (HID / 4) + idx];
        __syncthreads();

        // ================= phase 2: candidate + update =================
        #pragma unroll 8
        for (int k = 0; k < HID / 4; k++) {
            ulonglong2 rv0 = rh2[b0 * (HID / 4) + k];
            ulonglong2 rv1 = rh2[b1 * (HID / 4) + k];
            ulonglong2 wcv = wc2[k];
            ffma2(ac0, wcv.x, rv0.x); ffma2(ac0, wcv.y, rv0.y);
            ffma2(ac1, wcv.x, rv1.x); ffma2(ac1, wcv.y, rv1.y);
        }
        float c0 = tanhf_(f2sum(ac0) + sB[2 * HS + tx]);
        float c1 = tanhf_(f2sum(ac1) + sB[2 * HS + tx]);
        float hn0 = h0old + z0 * (c0 - h0old);   // (1-z)h + z*c
        float hn1 = h1old + z1 * (c1 - h1old);
        g_h[(bbase + b0) * HID + jg] = hn0;
        g_h[(bbase + b1) * HID + jg] = hn1;
        float* orow = out + (size_t)t * (BATCHN * HID);
        orow[(bbase + b0) * HID + jg] = hn0;
        orow[(bbase + b1) * HID + jg] = hn1;

        grid_arrive(sense);                      // barrier B (arrive)

        // overlap barrier B latency: prefetch x tile for t+1
        if (t + 1 < SEQLEN) {
            for (int idx = tid; idx < BT * (INPUTN / 4); idx += 256) {
                int row = idx >> 5, c4 = idx & 31;
                ((float4*)x_s)[row * 32 + c4] =
                    ((const float4*)X)[(size_t)(bbase + row) * (SEQLEN * INPUTN / 4)
                                       + (size_t)(t + 1) * (INPUTN / 4) + c4];
            }
        }

        grid_wait(sense);                        // barrier B (wait)

        // refresh h tile for next step
        if (t + 1 < SEQLEN) {
            for (int idx = tid; idx < BT * (HID / 4); idx += 256)
                ((float4*)h_s)[idx] = ((const float4*)g_h)[bbase * (HID / 4) + idx];
            __syncthreads();
        }
    }
}

extern "C" void kernel_launch(void* const* d_in, const int* in_sizes, int n_in,
                              void* d_out, int out_size) {
    const float* X  = (const float*)d_in[0];
    const float* Wz = (const float*)d_in[1];
    const float* bz = (const float*)d_in[2];
    const float* Wr = (const float*)d_in[3];
    const float* br = (const float*)d_in[4];
    const float* Wc = (const float*)d_in[5];
    const float* bc = (const float*)d_in[6];
    float* out = (float*)d_out;

    int smem_floats = 3 * HS * WPAD + 48 + BT * HID + BT * HID + BT * INPUTN;
    int smem_bytes  = smem_floats * (int)sizeof(float);   // 156,608 B

    cudaFuncSetAttribute(gru_persistent,
                         cudaFuncAttributeMaxDynamicSharedMemorySize, smem_bytes);
    gru_persistent<<<NBLK, 256, smem_bytes>>>(X, Wz, bz, Wr, br, Wc, bc, out);
}